// round 7
// baseline (speedup 1.0000x reference)
#include <cuda_runtime.h>
#include <math.h>

#define NN 20000
#define NE 640000
#define D  128
#define TEB 64   // edges per block
#define TN 32
#define FR 4224  // floats per fragment region (33 ksteps * 32 * 4)

typedef unsigned int u32;

// ---------------- scratch (static device memory; no allocations) ----------------
__device__ float g_hh[NN * D];
__device__ float g_agg[NN * D];
__device__ float g_aggx[NN * 3];
__device__ float g_e3[NE * 3];
// fragment-permuted tf32 weights: [s][nt][lane][2]
__device__ __align__(16) float g_Wa1p[33 * 16 * 64];
__device__ __align__(16) float g_We1p[33 * 16 * 64];  // fused [-We1|+We1|We1_e3]
__device__ __align__(16) float g_We2p[16 * 16 * 64];
__device__ __align__(16) float g_Wc1p[33 * 16 * 64];
__device__ __align__(16) float g_Wc2p[16 * 16 * 64];

__device__ __forceinline__ float siluf(float v) { return v / (1.f + expf(-v)); }

__device__ __forceinline__ u32 tf32r(float v) {
    u32 r;
    asm("cvt.rna.tf32.f32 %0, %1;" : "=r"(r) : "f"(v));
    return r;
}
__device__ __forceinline__ void mma8(float* c, uint4 a, uint2 b) {
    asm volatile(
        "mma.sync.aligned.m16n8k8.row.col.f32.tf32.tf32.f32 "
        "{%0,%1,%2,%3}, {%4,%5,%6,%7}, {%8,%9}, {%0,%1,%2,%3};"
        : "+f"(c[0]), "+f"(c[1]), "+f"(c[2]), "+f"(c[3])
        : "r"(a.x), "r"(a.y), "r"(a.z), "r"(a.w), "r"(b.x), "r"(b.y));
}
__device__ __forceinline__ void red2(float* p, float a, float b) {
    asm volatile("red.global.add.v2.f32 [%0], {%1, %2};"
                 :: "l"(p), "f"(a), "f"(b) : "memory");
}

// store (edge e in 0..63, feature k) into fragment-permuted A layout
__device__ __forceinline__ void stp(float* sA, int e, int k, float v) {
    float* base = sA + (e >> 4) * FR;
    int addr = (((k >> 3) * 32 + (((e & 7) << 2) | (k & 3))) << 2) +
               (((e & 8) >> 3) | ((k & 4) >> 1));
    ((u32*)base)[addr] = tf32r(v);
}

// ---------------- weight permute+tf32 prep ----------------
__global__ void prep_weights(const float* __restrict__ Wa1, const float* __restrict__ We1,
                             const float* __restrict__ We2, const float* __restrict__ Wc1,
                             const float* __restrict__ Wc2) {
    int m = blockIdx.y;
    const float* src; float* dst; int K, NS;
    if (m == 0)      { src = Wa1; dst = g_Wa1p; K = 259; NS = 33; }
    else if (m == 1) { src = We1; dst = g_We1p; K = 264; NS = 33; }
    else if (m == 2) { src = We2; dst = g_We2p; K = 128; NS = 16; }
    else if (m == 3) { src = Wc1; dst = g_Wc1p; K = 259; NS = 33; }
    else             { src = Wc2; dst = g_Wc2p; K = 128; NS = 16; }
    int idx = blockIdx.x * blockDim.x + threadIdx.x;
    if (idx >= NS * 16 * 32) return;
    int l = idx & 31, nt = (idx >> 5) & 15, s = idx >> 9;
    int k0 = s * 8 + (l & 3);
    int cc = nt * 8 + (l >> 2);
    float b0, b1;
    if (m == 1) {
        auto val = [&](int k) -> float {
            if (k < 128) return -src[k * 128 + cc];
            if (k < 259) return src[(k - 128) * 128 + cc];
            return 0.f;
        };
        b0 = val(k0);
        b1 = val(k0 + 4);
    } else {
        b0 = (k0 < K) ? src[k0 * 128 + cc] : 0.f;
        b1 = (k0 + 4 < K) ? src[(k0 + 4) * 128 + cc] : 0.f;
    }
    u32* d = (u32*)(dst + (s * 16 + nt) * 64 + l * 2);
    d[0] = tf32r(b0);
    d[1] = tf32r(b1);
}

__global__ void zero_scratch() {
    int idx = blockIdx.x * blockDim.x + threadIdx.x;
    int stride = gridDim.x * blockDim.x;
    for (int i = idx; i < NN * D; i += stride) g_agg[i] = 0.f;
    for (int i = idx; i < NN * 3; i += stride) g_aggx[i] = 0.f;
}

// ---------------- tf32 GEMM: 64 edges x 32 cols per warp ----------------
template <int NS>
__device__ __forceinline__ void gemm4(const float* sA, const float* __restrict__ gW,
                                      int lane, int w, float (*c)[4]) {
#pragma unroll 2
    for (int s = 0; s < NS; s++) {
        uint4 a[4];
#pragma unroll
        for (int mf = 0; mf < 4; mf++)
            a[mf] = ((const uint4*)(sA + mf * FR))[s * 32 + lane];
        uint2 b[4];
#pragma unroll
        for (int j = 0; j < 4; j++)
            b[j] = *(const uint2*)(gW + (s * 16 + w * 4 + j) * 64 + lane * 2);
#pragma unroll
        for (int mf = 0; mf < 4; mf++)
#pragma unroll
            for (int j = 0; j < 4; j++)
                mma8(c[mf * 4 + j], a[mf], b[j]);
    }
}
__device__ __forceinline__ void init_bias(const float* __restrict__ bias,
                                          int lane, int w, float (*c)[4]) {
#pragma unroll
    for (int j = 0; j < 4; j++) {
        float2 bb = *(const float2*)(bias + w * 32 + j * 8 + (lane & 3) * 2);
#pragma unroll
        for (int mf = 0; mf < 4; mf++) {
            c[mf * 4 + j][0] = bb.x; c[mf * 4 + j][1] = bb.y;
            c[mf * 4 + j][2] = bb.x; c[mf * 4 + j][3] = bb.y;
        }
    }
}

// ---------------- scalar FFMA GEMM (node kernels) ----------------
template <int TEc, int K, int LD>
__device__ __forceinline__ void mlp_layer(const float* __restrict__ W,
                                          const float* s_in, float bias,
                                          float* acc, int d) {
#pragma unroll
    for (int e = 0; e < TEc; e++) acc[e] = bias;
#pragma unroll 2
    for (int k = 0; k < K; k += 4) {
        float w0 = W[(k + 0) * D + d];
        float w1 = W[(k + 1) * D + d];
        float w2 = W[(k + 2) * D + d];
        float w3 = W[(k + 3) * D + d];
#pragma unroll
        for (int e = 0; e < TEc; e++) {
            float4 v = *(const float4*)(s_in + e * LD + k);
            acc[e] = fmaf(v.x, w0, acc[e]);
            acc[e] = fmaf(v.y, w1, acc[e]);
            acc[e] = fmaf(v.z, w2, acc[e]);
            acc[e] = fmaf(v.w, w3, acc[e]);
        }
    }
}

// ---------------- node linear ----------------
__global__ void node_lin(const float* __restrict__ h,
                         const float* __restrict__ Wlin,
                         const float* __restrict__ blin) {
    __shared__ __align__(16) float s_in[TN * D];
    int t = threadIdx.x;
    int r0 = blockIdx.x * TN;
    for (int e = 0; e < TN; e++) s_in[e * D + t] = h[(r0 + e) * D + t];
    __syncthreads();
    float acc[TN];
    mlp_layer<TN, 128, 128>(Wlin, s_in, blin[t], acc, t);
#pragma unroll
    for (int e = 0; e < TN; e++) g_hh[(r0 + e) * D + t] = acc[e];
}

// ---------------- edge message + attention (tf32 mma, 64-edge tile) -------------
__global__ void __launch_bounds__(128, 3)
edge_msg(const float* __restrict__ x, const int* __restrict__ ei,
         const float* __restrict__ edge_mask,
         const float* __restrict__ edge_attr,
         const float* __restrict__ be1, const float* __restrict__ be2,
         const float* __restrict__ ba1,
         const float* __restrict__ Wa2, const float* __restrict__ ba2) {
    extern __shared__ float sm[];
    float* sA    = sm;                   // 4*FR: att-in frags; reused for M1
    float* s_gp  = sA + 4 * FR;          // 256: gate partials [edge][warp]
    float* s_geo = s_gp + 256;           // 64
    float* s_at  = s_geo + 64;           // 64
    float* s_em  = s_at + 64;            // 64
    int*   s_row = (int*)(s_em + 64);    // 64
    int*   s_col = s_row + 64;           // 64

    int t = threadIdx.x, lane = t & 31, w = t >> 5;
    int e0b = blockIdx.x * TEB;

    if (t < TEB) {
        s_row[t] = ei[e0b + t];
        s_col[t] = ei[NE + e0b + t];
        s_em[t]  = edge_mask[e0b + t];
    }
    __syncthreads();

    // gather: warp w owns edges [w*16, w*16+16)
#pragma unroll
    for (int i = 0; i < 16; i++) {
        int e = w * 16 + i;
        int r = s_row[e], c = s_col[e];
        float q = 0.f;
#pragma unroll
        for (int pass = 0; pass < 4; pass++) {
            int k = pass * 32 + lane;
            float hr = g_hh[r * D + k];
            float hc = g_hh[c * D + k];
            stp(sA, e, k, hr);
            stp(sA, e, 128 + k, hc);
            float v = hc - hr;
            q = fmaf(v, v, q);
        }
#pragma unroll
        for (int o = 16; o > 0; o >>= 1) q += __shfl_down_sync(0xffffffffu, q, o);
        if (lane == 0) s_geo[e] = q;
    }
    __syncthreads();

    if (t < TEB) {
        int e = t;
        float geo = sqrtf(s_geo[e] + 1e-8f);
        int r = s_row[e], c = s_col[e];
        float dx = x[r * 3 + 0] - x[c * 3 + 0];
        float dy = x[r * 3 + 1] - x[c * 3 + 1];
        float dz = x[r * 3 + 2] - x[c * 3 + 2];
        float dist = sqrtf(dx * dx + dy * dy + dz * dz + 1e-8f);
        float ea = edge_attr[e0b + e];
        stp(sA, e, 256, dist);
        stp(sA, e, 257, ea);
        stp(sA, e, 258, geo);
#pragma unroll
        for (int k = 259; k < 264; k++) stp(sA, e, k, 0.f);
        g_e3[(e0b + e) * 3 + 0] = dist;
        g_e3[(e0b + e) * 3 + 1] = ea;
        g_e3[(e0b + e) * 3 + 2] = geo;
    }
    __syncthreads();

    // layer A1: att_in @ Wa1 -> gate partials
    {
        float cA[16][4];
        init_bias(ba1, lane, w, cA);
        gemm4<33>(sA, g_Wa1p, lane, w, cA);
        float p[8] = {0.f, 0.f, 0.f, 0.f, 0.f, 0.f, 0.f, 0.f};
#pragma unroll
        for (int j = 0; j < 4; j++) {
            float2 w2 = *(const float2*)(Wa2 + w * 32 + j * 8 + (lane & 3) * 2);
#pragma unroll
            for (int mf = 0; mf < 4; mf++) {
                p[mf * 2 + 0] += siluf(cA[mf * 4 + j][0]) * w2.x +
                                 siluf(cA[mf * 4 + j][1]) * w2.y;
                p[mf * 2 + 1] += siluf(cA[mf * 4 + j][2]) * w2.x +
                                 siluf(cA[mf * 4 + j][3]) * w2.y;
            }
        }
#pragma unroll
        for (int i = 0; i < 8; i++) {
            p[i] += __shfl_down_sync(0xffffffffu, p[i], 2, 4);
            p[i] += __shfl_down_sync(0xffffffffu, p[i], 1, 4);
        }
        if ((lane & 3) == 0) {
            int g = lane >> 2;
#pragma unroll
            for (int mf = 0; mf < 4; mf++) {
                s_gp[(mf * 16 + g) * 4 + w]     = p[mf * 2];
                s_gp[(mf * 16 + g + 8) * 4 + w] = p[mf * 2 + 1];
            }
        }
    }

    // layer M1 on SAME fragments via fused We1'
    float cM[16][4];
    init_bias(be1, lane, w, cM);
    gemm4<33>(sA, g_We1p, lane, w, cM);
    __syncthreads();  // all warps done reading sA / writing s_gp

    // write silu(M1) fragment-permuted into sA (alias); finalize att gate
#pragma unroll
    for (int j = 0; j < 4; j++) {
        int n = w * 32 + j * 8 + (lane & 3) * 2;
        int g = lane >> 2;
#pragma unroll
        for (int mf = 0; mf < 4; mf++) {
            int e = mf * 16 + g;
            stp(sA, e, n, siluf(cM[mf * 4 + j][0]));
            stp(sA, e, n + 1, siluf(cM[mf * 4 + j][1]));
            stp(sA, e + 8, n, siluf(cM[mf * 4 + j][2]));
            stp(sA, e + 8, n + 1, siluf(cM[mf * 4 + j][3]));
        }
    }
    if (t < TEB) {
        float z = s_gp[t * 4] + s_gp[t * 4 + 1] + s_gp[t * 4 + 2] + s_gp[t * 4 + 3]
                  + ba2[0];
        s_at[t] = s_em[t] / (1.f + expf(-z));
    }
    __syncthreads();

    // layer MSG: M1 @ We2 ; scale by att ; scatter
    float cO[16][4];
    init_bias(be2, lane, w, cO);
    gemm4<16>(sA, g_We2p, lane, w, cO);
#pragma unroll
    for (int j = 0; j < 4; j++) {
        int n = w * 32 + j * 8 + (lane & 3) * 2;
        int g = lane >> 2;
#pragma unroll
        for (int mf = 0; mf < 4; mf++) {
            int e = mf * 16 + g;
            float aL = s_at[e], aH = s_at[e + 8];
            red2(&g_agg[s_row[e] * D + n], cO[mf * 4 + j][0] * aL,
                 cO[mf * 4 + j][1] * aL);
            red2(&g_agg[s_row[e + 8] * D + n], cO[mf * 4 + j][2] * aH,
                 cO[mf * 4 + j][3] * aH);
        }
    }
}

// ---------------- node MLP + residual + LN + silu -> d_out ----------------
__global__ void node_mlp(const float* __restrict__ Wn1, const float* __restrict__ bn1,
                         const float* __restrict__ Wn2, const float* __restrict__ bn2,
                         const float* __restrict__ ln_g, const float* __restrict__ ln_b,
                         float* __restrict__ out_h) {
    __shared__ __align__(16) float s_a[TN * 128];
    __shared__ __align__(16) float s_t[TN * 128];
    __shared__ float s_mu[TN], s_rs[TN];
    int t = threadIdx.x, lane = t & 31, wid = t >> 5;
    int r0 = blockIdx.x * TN;

    for (int e = 0; e < TN; e++) s_a[e * 128 + t] = g_agg[(r0 + e) * D + t];
    __syncthreads();

    float acc[TN];
    mlp_layer<TN, 128, 128>(Wn1, s_a, bn1[t], acc, t);
#pragma unroll
    for (int e = 0; e < TN; e++) s_t[e * 128 + t] = siluf(acc[e]);
    __syncthreads();

    mlp_layer<TN, 128, 128>(Wn2, s_t, bn2[t], acc, t);
#pragma unroll
    for (int e = 0; e < TN; e++) {
        float v = g_hh[(r0 + e) * D + t] + acc[e];
        s_a[e * 128 + t] = v;
    }
    __syncthreads();

    for (int i = 0; i < TN / 4; i++) {
        int e = wid * (TN / 4) + i;
        float v0 = s_a[e * 128 + lane];
        float v1 = s_a[e * 128 + lane + 32];
        float v2 = s_a[e * 128 + lane + 64];
        float v3 = s_a[e * 128 + lane + 96];
        float s = v0 + v1 + v2 + v3;
        float q = v0 * v0 + v1 * v1 + v2 * v2 + v3 * v3;
#pragma unroll
        for (int o = 16; o > 0; o >>= 1) {
            s += __shfl_down_sync(0xffffffffu, s, o);
            q += __shfl_down_sync(0xffffffffu, q, o);
        }
        if (lane == 0) {
            float mu = s * (1.f / 128.f);
            float var = q * (1.f / 128.f) - mu * mu;
            s_mu[e] = mu;
            s_rs[e] = rsqrtf(var + 1e-5f);
        }
    }
    __syncthreads();

    float g = ln_g[t], bb = ln_b[t];
    for (int e = 0; e < TN; e++) {
        float v = (s_a[e * 128 + t] - s_mu[e]) * s_rs[e] * g + bb;
        out_h[(r0 + e) * D + t] = siluf(v);
    }
}

// ---------------- coord MLP + scatter (tf32 mma, 64-edge tile) ----------------
__global__ void __launch_bounds__(128, 3)
edge_coord(const float* __restrict__ x, const int* __restrict__ ei,
           const float* __restrict__ edge_mask,
           const float* __restrict__ hh2,
           const float* __restrict__ bc1, const float* __restrict__ bc2,
           const float* __restrict__ Wc3) {
    extern __shared__ float sm[];
    float* sA    = sm;                   // 4*FR; reused for M1
    float* s_gp  = sA + 4 * FR;          // 256
    float* s_em  = s_gp + 256;           // 64
    float* s_d   = s_em + 64;            // 64
    int*   s_row = (int*)(s_d + 64);     // 64
    int*   s_col = s_row + 64;           // 64

    int t = threadIdx.x, lane = t & 31, w = t >> 5;
    int e0b = blockIdx.x * TEB;

    if (t < TEB) {
        s_row[t] = ei[e0b + t];
        s_col[t] = ei[NE + e0b + t];
        s_em[t]  = edge_mask[e0b + t];
    }
    __syncthreads();

#pragma unroll
    for (int i = 0; i < 16; i++) {
        int e = w * 16 + i;
        int r = s_row[e], c = s_col[e];
#pragma unroll
        for (int pass = 0; pass < 4; pass++) {
            int k = pass * 32 + lane;
            stp(sA, e, k, hh2[r * D + k]);
            stp(sA, e, 128 + k, hh2[c * D + k]);
        }
    }
    if (t < TEB) {
        int e = t;
        float dist = g_e3[(e0b + e) * 3 + 0];
        float ea   = g_e3[(e0b + e) * 3 + 1];
        float geo  = g_e3[(e0b + e) * 3 + 2];
        stp(sA, e, 256, dist);
        stp(sA, e, 257, ea);
        stp(sA, e, 258, geo);
#pragma unroll
        for (int k = 259; k < 264; k++) stp(sA, e, k, 0.f);
        s_d[e] = dist;
    }
    __syncthreads();

    float c1[16][4];
    init_bias(bc1, lane, w, c1);
    gemm4<33>(sA, g_Wc1p, lane, w, c1);
    __syncthreads();  // everyone done reading sA

#pragma unroll
    for (int j = 0; j < 4; j++) {
        int n = w * 32 + j * 8 + (lane & 3) * 2;
        int g = lane >> 2;
#pragma unroll
        for (int mf = 0; mf < 4; mf++) {
            int e = mf * 16 + g;
            stp(sA, e, n, siluf(c1[mf * 4 + j][0]));
            stp(sA, e, n + 1, siluf(c1[mf * 4 + j][1]));
            stp(sA, e + 8, n, siluf(c1[mf * 4 + j][2]));
            stp(sA, e + 8, n + 1, siluf(c1[mf * 4 + j][3]));
        }
    }
    __syncthreads();

    float c2[16][4];
    init_bias(bc2, lane, w, c2);
    gemm4<16>(sA, g_Wc2p, lane, w, c2);

    // m = silu(M2) @ Wc3 via fragment reduction
    {
        float p[8] = {0.f, 0.f, 0.f, 0.f, 0.f, 0.f, 0.f, 0.f};
#pragma unroll
        for (int j = 0; j < 4; j++) {
            float2 w3 = *(const float2*)(Wc3 + w * 32 + j * 8 + (lane & 3) * 2);
#pragma unroll
            for (int mf = 0; mf < 4; mf++) {
                p[mf * 2 + 0] += siluf(c2[mf * 4 + j][0]) * w3.x +
                                 siluf(c2[mf * 4 + j][1]) * w3.y;
                p[mf * 2 + 1] += siluf(c2[mf * 4 + j][2]) * w3.x +
                                 siluf(c2[mf * 4 + j][3]) * w3.y;
            }
        }
#pragma unroll
        for (int i = 0; i < 8; i++) {
            p[i] += __shfl_down_sync(0xffffffffu, p[i], 2, 4);
            p[i] += __shfl_down_sync(0xffffffffu, p[i], 1, 4);
        }
        if ((lane & 3) == 0) {
            int g = lane >> 2;
#pragma unroll
            for (int mf = 0; mf < 4; mf++) {
                s_gp[(mf * 16 + g) * 4 + w]     = p[mf * 2];
                s_gp[(mf * 16 + g + 8) * 4 + w] = p[mf * 2 + 1];
            }
        }
    }
    __syncthreads();

    if (t < TEB) {
        int e = t;
        float mval = (s_gp[e * 4] + s_gp[e * 4 + 1] + s_gp[e * 4 + 2] + s_gp[e * 4 + 3])
                     * s_em[e];
        int r = s_row[e], c = s_col[e];
        float dx = x[r * 3 + 0] - x[c * 3 + 0];
        float dy = x[r * 3 + 1] - x[c * 3 + 1];
        float dz = x[r * 3 + 2] - x[c * 3 + 2];
        float inv = 1.f / (s_d[e] + 1.f);
        atomicAdd(&g_aggx[r * 3 + 0], dx * inv * mval);
        atomicAdd(&g_aggx[r * 3 + 1], dy * inv * mval);
        atomicAdd(&g_aggx[r * 3 + 2], dz * inv * mval);
    }
}

__global__ void finalize_x(const float* __restrict__ x,
                           const float* __restrict__ node_mask,
                           float* __restrict__ out) {
    int i = blockIdx.x * blockDim.x + threadIdx.x;
    if (i < NN * 3) {
        out[i] = (x[i] + g_aggx[i] * (1.f / 100.f)) * node_mask[i / 3];
    }
}

// ---------------- launcher ----------------
extern "C" void kernel_launch(void* const* d_in, const int* in_sizes, int n_in,
                              void* d_out, int out_size) {
    const float* h         = (const float*)d_in[0];
    const float* x         = (const float*)d_in[1];
    const int*   ei        = (const int*)d_in[2];
    const float* node_mask = (const float*)d_in[3];
    const float* edge_mask = (const float*)d_in[4];
    const float* edge_attr = (const float*)d_in[5];
    const float* Wlin = (const float*)d_in[6];
    const float* blin = (const float*)d_in[7];
    const float* We1  = (const float*)d_in[8];
    const float* be1  = (const float*)d_in[9];
    const float* We2  = (const float*)d_in[10];
    const float* be2  = (const float*)d_in[11];
    const float* Wn1  = (const float*)d_in[12];
    const float* bn1  = (const float*)d_in[13];
    const float* Wn2  = (const float*)d_in[14];
    const float* bn2  = (const float*)d_in[15];
    const float* Wa1  = (const float*)d_in[16];
    const float* ba1  = (const float*)d_in[17];
    const float* Wa2  = (const float*)d_in[18];
    const float* ba2  = (const float*)d_in[19];
    const float* ln_g = (const float*)d_in[20];
    const float* ln_b = (const float*)d_in[21];
    const float* Wc1  = (const float*)d_in[22];
    const float* bc1  = (const float*)d_in[23];
    const float* Wc2  = (const float*)d_in[24];
    const float* bc2  = (const float*)d_in[25];
    const float* Wc3  = (const float*)d_in[26];
    float* out = (float*)d_out;

    const int SMEM_MSG = (4 * FR + 256 + 64 + 64 + 64) * 4 + 2 * 64 * 4;
    const int SMEM_CRD = (4 * FR + 256 + 64 + 64) * 4 + 2 * 64 * 4;

    cudaFuncSetAttribute(edge_msg, cudaFuncAttributeMaxDynamicSharedMemorySize, SMEM_MSG);
    cudaFuncSetAttribute(edge_coord, cudaFuncAttributeMaxDynamicSharedMemorySize, SMEM_CRD);

    prep_weights<<<dim3(66, 5), 256>>>(Wa1, We1, We2, Wc1, Wc2);
    zero_scratch<<<1024, 256>>>();
    node_lin<<<NN / TN, 128>>>(h, Wlin, blin);
    edge_msg<<<NE / TEB, 128, SMEM_MSG>>>(x, ei, edge_mask, edge_attr,
                                          be1, be2, ba1, Wa2, ba2);
    node_mlp<<<NN / TN, 128>>>(Wn1, bn1, Wn2, bn2, ln_g, ln_b, out);
    edge_coord<<<NE / TEB, 128, SMEM_CRD>>>(x, ei, edge_mask, out, bc1, bc2, Wc3);
    finalize_x<<<(NN * 3 + 255) / 256, 256>>>(x, node_mask, out + NN * D);
}